// round 1
// baseline (speedup 1.0000x reference)
#include <cuda_runtime.h>
#include <math.h>

#define N_ATOMS 50000
#define M_NBR   12
#define A_DIM   128
#define NBR_DIM 64
#define NM_ROWS (N_ATOMS * M_NBR)
#define EPS_F   1e-5f

// ---------------- scratch (static device globals; no allocation) ----------------
__device__ float  g_P[(size_t)N_ATOMS * 512];   // [i][0:256)=atom@W1, [256:512)=atom@W2
__device__ float  g_Y[(size_t)NM_ROWS * 256];   // pre-BN gated features (masked rows only valid)
__device__ float  g_NS[(size_t)N_ATOMS * 128];  // nbr_sumed
__device__ double g_sum1[256];
__device__ double g_sq1[256];
__device__ double g_cnt;
__device__ double g_sum2[128];
__device__ double g_sq2[128];
__device__ float  g_sc1[256], g_sh1[256];
__device__ float  g_sc2[128], g_sh2[128];

// ---------------- helpers ----------------
__device__ __forceinline__ float softplus_f(float x) {
    return fmaxf(x, 0.f) + log1pf(__expf(-fabsf(x)));
}
__device__ __forceinline__ float sigmoid_f(float x) {
    return 1.f / (1.f + __expf(-x));
}

// ---------------- kernel 0: zero the accumulators (graph-replay safe) ----------------
__global__ void k_zero() {
    int t = threadIdx.x;
    if (t < 256) { g_sum1[t] = 0.0; g_sq1[t] = 0.0; }
    if (t < 128) { g_sum2[t] = 0.0; g_sq2[t] = 0.0; }
    if (t == 0)  g_cnt = 0.0;
}

// ---------------- kernel 1: P = atom_in @ [W1 | W2]  (50000x128 @ 128x512) ----------------
// grid (391, 4), block 256. tn: 0,1 -> W rows [0:128); 2,3 -> W rows [128:256)
__global__ void k_gemmP(const float* __restrict__ atom, const float* __restrict__ W) {
    __shared__ float As[16][128];
    __shared__ float Bs[16][128];
    int tm   = blockIdx.x;
    int tn   = blockIdx.y;
    int koff = (tn >= 2) ? 128 : 0;
    int cbase = (tn & 1) * 128;
    int im0  = tm * 128;
    int t  = threadIdx.x;
    int tx = t & 15, ty = t >> 4;

    float acc[8][8];
#pragma unroll
    for (int i = 0; i < 8; i++)
#pragma unroll
        for (int j = 0; j < 8; j++) acc[i][j] = 0.f;

    for (int kt = 0; kt < 128; kt += 16) {
#pragma unroll
        for (int l = 0; l < 2; l++) {
            int id  = t + l * 256;          // 0..511
            int k4  = (id & 3) * 4;
            int row = id >> 2;              // 0..127
            int gr  = im0 + row;
            float4 v = make_float4(0.f, 0.f, 0.f, 0.f);
            if (gr < N_ATOMS) v = *(const float4*)&atom[(size_t)gr * 128 + kt + k4];
            As[k4    ][row] = v.x;
            As[k4 + 1][row] = v.y;
            As[k4 + 2][row] = v.z;
            As[k4 + 3][row] = v.w;
        }
#pragma unroll
        for (int l = 0; l < 2; l++) {
            int id = t + l * 256;
            int c4 = (id & 31) * 4;
            int k  = id >> 5;               // 0..15
            *(float4*)&Bs[k][c4] = *(const float4*)&W[(size_t)(koff + kt + k) * 256 + cbase + c4];
        }
        __syncthreads();
#pragma unroll
        for (int k = 0; k < 16; k++) {
            float a[8], b[8];
            *(float4*)&a[0] = *(float4*)&As[k][ty * 8];
            *(float4*)&a[4] = *(float4*)&As[k][ty * 8 + 4];
            *(float4*)&b[0] = *(float4*)&Bs[k][tx * 8];
            *(float4*)&b[4] = *(float4*)&Bs[k][tx * 8 + 4];
#pragma unroll
            for (int i = 0; i < 8; i++)
#pragma unroll
                for (int j = 0; j < 8; j++) acc[i][j] += a[i] * b[j];
        }
        __syncthreads();
    }
#pragma unroll
    for (int i = 0; i < 8; i++) {
        int gr = im0 + ty * 8 + i;
        if (gr < N_ATOMS) {
            size_t base = (size_t)gr * 512 + tn * 128 + tx * 8;
            *(float4*)&g_P[base]     = make_float4(acc[i][0], acc[i][1], acc[i][2], acc[i][3]);
            *(float4*)&g_P[base + 4] = make_float4(acc[i][4], acc[i][5], acc[i][6], acc[i][7]);
        }
    }
}

// ---------------- kernel 2: fused edge GEMM (K=64) + gather P1/P2 + bias; masked Y store + BN1 stats ----------------
// grid (1250, 2) block 128. blockIdx.y = column half (0 or 1).
// Warp layout: lane%8 -> col group (4 cols), lane/8 -> atom lane (4 atoms per block).
#define NFSTRIDE 776   // 768 + 8 pad to break LDS bank conflicts across atom lanes
__global__ void k_fuseY(const float* __restrict__ nbr_fea, const int* __restrict__ nbr_idx,
                        const float* __restrict__ mask, const float* __restrict__ W,
                        const float* __restrict__ bfc) {
    __shared__ float W3s[64 * 128];       // 32 KB: W rows 256..319, this block's 128-col half
    __shared__ float nfs[4 * NFSTRIDE];   // 4 atoms x 64 feats x 12 nbrs
    __shared__ float ssum[128], ssq[128];
    __shared__ int   idxs[48];
    __shared__ float msks[48];

    int t    = threadIdx.x;       // 0..127
    int lane = t & 31, w = t >> 5;
    int cg   = w * 8 + (lane & 7);   // 0..31 col group within the half
    int ta   = lane >> 3;            // 0..3 atom lane
    int half = blockIdx.y;
    int C0   = half * 128 + cg * 4;  // global column of first of my 4 cols

    // load this half of W3 (rows 256..319 of W_fc)
    for (int l = t; l < 2048; l += 128) {      // 8192 floats / 4
        int k = l >> 5;
        int c = l & 31;
        *(float4*)&W3s[k * 128 + c * 4] =
            *(const float4*)&W[(size_t)(256 + k) * 256 + half * 128 + c * 4];
    }
    ssum[t] = 0.f; ssq[t] = 0.f;

    float4 bb = *(const float4*)&bfc[C0];
    float4 rs = make_float4(0.f, 0.f, 0.f, 0.f);
    float4 rq = make_float4(0.f, 0.f, 0.f, 0.f);
    float  cntloc = 0.f;

    for (int i0 = blockIdx.x * 4; i0 < N_ATOMS; i0 += gridDim.x * 4) {
        __syncthreads();  // protect smem staging vs previous iteration readers
        // stage nbr_fea for 4 atoms (3072 floats)
        for (int l = t; l < 768; l += 128) {
            int aidx = l / 192, off = l % 192;
            int gi = i0 + aidx;
            float4 v = make_float4(0.f, 0.f, 0.f, 0.f);
            if (gi < N_ATOMS) v = *(const float4*)&nbr_fea[(size_t)gi * 768 + off * 4];
            *(float4*)&nfs[aidx * NFSTRIDE + off * 4] = v;
        }
        if (t < 48) {
            int aidx = t / 12, j = t % 12;
            int gi = i0 + aidx;
            idxs[t] = (gi < N_ATOMS) ? nbr_idx[gi * 12 + j] : 0;
            msks[t] = (gi < N_ATOMS) ? mask[gi * 12 + j] : 0.f;
        }
        __syncthreads();

        int i = i0 + ta;
        if (i < N_ATOMS) {
            float4 p1 = *(const float4*)&g_P[(size_t)i * 512 + C0];
            const float* nfa = &nfs[ta * NFSTRIDE];
#pragma unroll 1
            for (int j = 0; j < 12; j++) {
                float mk = msks[ta * 12 + j];
                if (mk <= 0.5f) continue;   // unmasked rows are never consumed downstream
                float4 acc = make_float4(0.f, 0.f, 0.f, 0.f);
                const float* nfj = &nfa[j * 64];
#pragma unroll
                for (int k = 0; k < 64; k += 4) {
                    float4 nf = *(const float4*)&nfj[k];
                    float4 w0 = *(const float4*)&W3s[(k + 0) * 128 + cg * 4];
                    acc.x += nf.x * w0.x; acc.y += nf.x * w0.y; acc.z += nf.x * w0.z; acc.w += nf.x * w0.w;
                    float4 w1 = *(const float4*)&W3s[(k + 1) * 128 + cg * 4];
                    acc.x += nf.y * w1.x; acc.y += nf.y * w1.y; acc.z += nf.y * w1.z; acc.w += nf.y * w1.w;
                    float4 w2 = *(const float4*)&W3s[(k + 2) * 128 + cg * 4];
                    acc.x += nf.z * w2.x; acc.y += nf.z * w2.y; acc.z += nf.z * w2.z; acc.w += nf.z * w2.w;
                    float4 w3 = *(const float4*)&W3s[(k + 3) * 128 + cg * 4];
                    acc.x += nf.w * w3.x; acc.y += nf.w * w3.y; acc.z += nf.w * w3.z; acc.w += nf.w * w3.w;
                }
                int nb = idxs[ta * 12 + j];
                float4 p2 = *(const float4*)&g_P[(size_t)nb * 512 + 256 + C0];
                float4 y;
                y.x = acc.x + p1.x + p2.x + bb.x;
                y.y = acc.y + p1.y + p2.y + bb.y;
                y.z = acc.z + p1.z + p2.z + bb.z;
                y.w = acc.w + p1.w + p2.w + bb.w;
                size_t row = (size_t)i * 12 + j;
                *(float4*)&g_Y[row * 256 + C0] = y;
                rs.x += y.x; rs.y += y.y; rs.z += y.z; rs.w += y.w;
                rq.x += y.x * y.x; rq.y += y.y * y.y; rq.z += y.z * y.z; rq.w += y.w * y.w;
            }
        }
        if (half == 0 && t == 0) {
            float s = 0.f;
            for (int q = 0; q < 48; q++) s += msks[q];
            cntloc += s;
        }
    }

    __syncthreads();
    int cb = cg * 4;
    atomicAdd(&ssum[cb    ], rs.x); atomicAdd(&ssq[cb    ], rq.x);
    atomicAdd(&ssum[cb + 1], rs.y); atomicAdd(&ssq[cb + 1], rq.y);
    atomicAdd(&ssum[cb + 2], rs.z); atomicAdd(&ssq[cb + 2], rq.z);
    atomicAdd(&ssum[cb + 3], rs.w); atomicAdd(&ssq[cb + 3], rq.w);
    __syncthreads();
    atomicAdd(&g_sum1[half * 128 + t], (double)ssum[t]);
    atomicAdd(&g_sq1 [half * 128 + t], (double)ssq[t]);
    if (half == 0 && t == 0) atomicAdd(&g_cnt, (double)cntloc);
}

// ---------------- kernel 3: finalize BN1 -> per-column affine ----------------
__global__ void k_fin1(const float* __restrict__ gamma1, const float* __restrict__ beta1) {
    int c = threadIdx.x;  // 256
    double cnt = g_cnt;
    double m = g_sum1[c] / cnt;
    double v = g_sq1[c] / cnt - m * m;
    float sc = gamma1[c] * rsqrtf(fmaxf((float)v, 0.f) + EPS_F);
    g_sc1[c] = sc;
    g_sh1[c] = beta1[c] - (float)m * sc;
}

// ---------------- kernel 4: BN1 affine + sigmoid*softplus, masked sum over neighbors ----------------
__global__ void k_act(const float* __restrict__ mask) {
    int i = blockIdx.x;
    int c = threadIdx.x;  // 128
    float scf = g_sc1[c],       shf = g_sh1[c];
    float scc = g_sc1[128 + c], shc = g_sh1[128 + c];
    float s = 0.f;
#pragma unroll 1
    for (int j = 0; j < 12; j++) {
        float mk = mask[i * 12 + j];
        if (mk > 0.5f) {
            size_t row = (size_t)i * 12 + j;
            float yf = g_Y[row * 256 + c]       * scf + shf;
            float yc = g_Y[row * 256 + 128 + c] * scc + shc;
            s += sigmoid_f(yf) * softplus_f(yc);
        }
    }
    g_NS[(size_t)i * 128 + c] = s;
}

// ---------------- kernel 5: BN2 stats ----------------
__global__ void k_stats2() {
    int c = threadIdx.x;  // 128
    float s = 0.f, q = 0.f;
    for (int i = blockIdx.x; i < N_ATOMS; i += gridDim.x) {
        float v = g_NS[(size_t)i * 128 + c];
        s += v; q += v * v;
    }
    atomicAdd(&g_sum2[c], (double)s);
    atomicAdd(&g_sq2[c],  (double)q);
}

// ---------------- kernel 6: finalize BN2 ----------------
__global__ void k_fin2(const float* __restrict__ gamma2, const float* __restrict__ beta2) {
    int c = threadIdx.x;  // 128
    double m = g_sum2[c] / (double)N_ATOMS;
    double v = g_sq2[c] / (double)N_ATOMS - m * m;
    float sc = gamma2[c] * rsqrtf(fmaxf((float)v, 0.f) + EPS_F);
    g_sc2[c] = sc;
    g_sh2[c] = beta2[c] - (float)m * sc;
}

// ---------------- kernel 7: output = softplus(atom + BN2(nbr_sumed)) ----------------
__global__ void k_out(const float* __restrict__ atom, float* __restrict__ out) {
    int idx = blockIdx.x * blockDim.x + threadIdx.x;
    if (idx < N_ATOMS * 128) {
        int c = idx & 127;
        float v = g_NS[idx] * g_sc2[c] + g_sh2[c] + atom[idx];
        out[idx] = softplus_f(v);
    }
}

// ---------------- launcher ----------------
extern "C" void kernel_launch(void* const* d_in, const int* in_sizes, int n_in,
                              void* d_out, int out_size) {
    const float* atom    = (const float*)d_in[0];
    const float* nbr_fea = (const float*)d_in[1];
    const int*   nbr_idx = (const int*)  d_in[2];
    const float* mask    = (const float*)d_in[3];
    const float* W       = (const float*)d_in[4];
    const float* b       = (const float*)d_in[5];
    const float* gamma1  = (const float*)d_in[6];
    const float* beta1   = (const float*)d_in[7];
    const float* gamma2  = (const float*)d_in[8];
    const float* beta2   = (const float*)d_in[9];
    float* out = (float*)d_out;

    k_zero  <<<1, 256>>>();
    k_gemmP <<<dim3(391, 4), 256>>>(atom, W);
    k_fuseY <<<dim3(1250, 2), 128>>>(nbr_fea, nbr_idx, mask, W, b);
    k_fin1  <<<1, 256>>>(gamma1, beta1);
    k_act   <<<N_ATOMS, 128>>>(mask);
    k_stats2<<<256, 128>>>();
    k_fin2  <<<1, 128>>>(gamma2, beta2);
    k_out   <<<(N_ATOMS * 128 + 255) / 256, 256>>>(atom, out);
}

// round 2
// speedup vs baseline: 1.6928x; 1.6928x over previous
#include <cuda_runtime.h>
#include <math.h>

#define N_ATOMS 50000
#define M_NBR   12
#define A_DIM   128
#define NBR_DIM 64
#define NM_ROWS (N_ATOMS * M_NBR)
#define EPS_F   1e-5f

// ---------------- scratch (static device globals; no allocation) ----------------
__device__ float  g_P[(size_t)N_ATOMS * 512];   // [i][0:256)=atom@W1, [256:512)=atom@W2
__device__ float  g_Y[(size_t)NM_ROWS * 256];   // pre-BN gated features (masked rows only valid)
__device__ float  g_NS[(size_t)N_ATOMS * 128];  // nbr_sumed
__device__ int    g_nedges;
__device__ int2   g_edges[NM_ROWS];             // (.x = i*12+j, .y = nbr index)
__device__ double g_sum1[256];
__device__ double g_sq1[256];
__device__ double g_sum2[128];
__device__ double g_sq2[128];
__device__ float  g_sc1[256], g_sh1[256];
__device__ float  g_sc2[128], g_sh2[128];

// ---------------- helpers ----------------
__device__ __forceinline__ float softplus_f(float x) {
    return fmaxf(x, 0.f) + log1pf(__expf(-fabsf(x)));
}
__device__ __forceinline__ float sigmoid_f(float x) {
    return 1.f / (1.f + __expf(-x));
}

// ---------------- kernel 0: zero accumulators (graph-replay safe) ----------------
__global__ void k_zero() {
    int t = threadIdx.x;
    if (t < 256) { g_sum1[t] = 0.0; g_sq1[t] = 0.0; }
    if (t < 128) { g_sum2[t] = 0.0; g_sq2[t] = 0.0; }
    if (t == 0)  g_nedges = 0;
}

// ---------------- kernel 1: edge compaction (masked rows only) ----------------
__global__ void k_compact(const float* __restrict__ mask, const int* __restrict__ nbr_idx) {
    int t = blockIdx.x * blockDim.x + threadIdx.x;
    if (t < NM_ROWS && mask[t] > 0.5f) {
        int p = atomicAdd(&g_nedges, 1);
        g_edges[p] = make_int2(t, nbr_idx[t]);
    }
}

// ---------------- kernel 2: P = atom_in @ [W1 | W2]  (50000x128 @ 128x512) ----------------
__global__ void k_gemmP(const float* __restrict__ atom, const float* __restrict__ W) {
    __shared__ float As[16][128];
    __shared__ float Bs[16][128];
    int tm   = blockIdx.x;
    int tn   = blockIdx.y;
    int koff = (tn >= 2) ? 128 : 0;
    int cbase = (tn & 1) * 128;
    int im0  = tm * 128;
    int t  = threadIdx.x;
    int tx = t & 15, ty = t >> 4;

    float acc[8][8];
#pragma unroll
    for (int i = 0; i < 8; i++)
#pragma unroll
        for (int j = 0; j < 8; j++) acc[i][j] = 0.f;

    for (int kt = 0; kt < 128; kt += 16) {
#pragma unroll
        for (int l = 0; l < 2; l++) {
            int id  = t + l * 256;
            int k4  = (id & 3) * 4;
            int row = id >> 2;
            int gr  = im0 + row;
            float4 v = make_float4(0.f, 0.f, 0.f, 0.f);
            if (gr < N_ATOMS) v = *(const float4*)&atom[(size_t)gr * 128 + kt + k4];
            As[k4    ][row] = v.x;
            As[k4 + 1][row] = v.y;
            As[k4 + 2][row] = v.z;
            As[k4 + 3][row] = v.w;
        }
#pragma unroll
        for (int l = 0; l < 2; l++) {
            int id = t + l * 256;
            int c4 = (id & 31) * 4;
            int k  = id >> 5;
            *(float4*)&Bs[k][c4] = *(const float4*)&W[(size_t)(koff + kt + k) * 256 + cbase + c4];
        }
        __syncthreads();
#pragma unroll
        for (int k = 0; k < 16; k++) {
            float a[8], b[8];
            *(float4*)&a[0] = *(float4*)&As[k][ty * 8];
            *(float4*)&a[4] = *(float4*)&As[k][ty * 8 + 4];
            *(float4*)&b[0] = *(float4*)&Bs[k][tx * 8];
            *(float4*)&b[4] = *(float4*)&Bs[k][tx * 8 + 4];
#pragma unroll
            for (int i = 0; i < 8; i++)
#pragma unroll
                for (int j = 0; j < 8; j++) acc[i][j] += a[i] * b[j];
        }
        __syncthreads();
    }
#pragma unroll
    for (int i = 0; i < 8; i++) {
        int gr = im0 + ty * 8 + i;
        if (gr < N_ATOMS) {
            size_t base = (size_t)gr * 512 + tn * 128 + tx * 8;
            *(float4*)&g_P[base]     = make_float4(acc[i][0], acc[i][1], acc[i][2], acc[i][3]);
            *(float4*)&g_P[base + 4] = make_float4(acc[i][4], acc[i][5], acc[i][6], acc[i][7]);
        }
    }
}

// ---------------- kernel 3: compacted edge GEMM (K=64) + P1/P2 gather + bias + BN1 stats ----------------
// block 128 = 8 edge-pair lanes x 16 col-groups (8 cols). blockIdx.y = column half.
#define ETILE 16
#define NFSTR 68
__global__ void k_edge(const float* __restrict__ nbr_fea, const float* __restrict__ W,
                       const float* __restrict__ bfc) {
    __shared__ float W3s[64 * 128];       // 32 KB
    __shared__ float nfs[ETILE * NFSTR];  // 16 edges x 64 feats (padded)
    __shared__ float ssum[128], ssq[128];

    int t    = threadIdx.x;   // 0..127
    int elp  = t & 7;         // edge-pair lane
    int cq   = t >> 3;        // 0..15
    int half = blockIdx.y;
    int c0   = cq * 8;        // first of my 8 cols within the half

    for (int l = t; l < 2048; l += 128) {
        int k = l >> 5, c4 = (l & 31) * 4;
        *(float4*)&W3s[k * 128 + c4] =
            *(const float4*)&W[(size_t)(256 + k) * 256 + half * 128 + c4];
    }
    ssum[t] = 0.f; ssq[t] = 0.f;

    float4 bb0 = *(const float4*)&bfc[half * 128 + c0];
    float4 bb1 = *(const float4*)&bfc[half * 128 + c0 + 4];

    float rs[8], rq[8];
#pragma unroll
    for (int q = 0; q < 8; q++) { rs[q] = 0.f; rq[q] = 0.f; }

    int ne = g_nedges;
    for (int e0 = blockIdx.x * ETILE; e0 < ne; e0 += gridDim.x * ETILE) {
        __syncthreads();
        // stage nbr_fea for 16 edges (1024 floats = 256 float4 by 128 threads x2)
        for (int l = t; l < 256; l += 128) {
            int e = l >> 4, k4 = (l & 15) * 4;
            int eg = e0 + e;
            if (eg < ne) {
                int ex = g_edges[eg].x;
                *(float4*)&nfs[e * NFSTR + k4] =
                    *(const float4*)&nbr_fea[(size_t)ex * 64 + k4];
            }
        }
        __syncthreads();

        int eA = e0 + elp * 2;
        int eB = eA + 1;
        bool vA = eA < ne, vB = eB < ne;
        int2 edA = vA ? g_edges[eA] : make_int2(0, 0);
        int2 edB = vB ? g_edges[eB] : make_int2(0, 0);
        int iA = edA.x / 12, iB = edB.x / 12;

        float accA[8], accB[8];
        {
            float4 p1 = *(const float4*)&g_P[(size_t)iA * 512 + half * 128 + c0];
            float4 p2 = *(const float4*)&g_P[(size_t)edA.y * 512 + 256 + half * 128 + c0];
            accA[0] = bb0.x + p1.x + p2.x; accA[1] = bb0.y + p1.y + p2.y;
            accA[2] = bb0.z + p1.z + p2.z; accA[3] = bb0.w + p1.w + p2.w;
            float4 p3 = *(const float4*)&g_P[(size_t)iA * 512 + half * 128 + c0 + 4];
            float4 p4 = *(const float4*)&g_P[(size_t)edA.y * 512 + 256 + half * 128 + c0 + 4];
            accA[4] = bb1.x + p3.x + p4.x; accA[5] = bb1.y + p3.y + p4.y;
            accA[6] = bb1.z + p3.z + p4.z; accA[7] = bb1.w + p3.w + p4.w;
        }
        {
            float4 p1 = *(const float4*)&g_P[(size_t)iB * 512 + half * 128 + c0];
            float4 p2 = *(const float4*)&g_P[(size_t)edB.y * 512 + 256 + half * 128 + c0];
            accB[0] = bb0.x + p1.x + p2.x; accB[1] = bb0.y + p1.y + p2.y;
            accB[2] = bb0.z + p1.z + p2.z; accB[3] = bb0.w + p1.w + p2.w;
            float4 p3 = *(const float4*)&g_P[(size_t)iB * 512 + half * 128 + c0 + 4];
            float4 p4 = *(const float4*)&g_P[(size_t)edB.y * 512 + 256 + half * 128 + c0 + 4];
            accB[4] = bb1.x + p3.x + p4.x; accB[5] = bb1.y + p3.y + p4.y;
            accB[6] = bb1.z + p3.z + p4.z; accB[7] = bb1.w + p3.w + p4.w;
        }

        const float* nfA = &nfs[(elp * 2) * NFSTR];
        const float* nfB = nfA + NFSTR;
#pragma unroll
        for (int k = 0; k < 64; k += 4) {
            float4 a = *(const float4*)&nfA[k];
            float4 b = *(const float4*)&nfB[k];
            float av[4] = {a.x, a.y, a.z, a.w};
            float bv[4] = {b.x, b.y, b.z, b.w};
#pragma unroll
            for (int kk = 0; kk < 4; kk++) {
                float4 w0 = *(const float4*)&W3s[(k + kk) * 128 + c0];
                float4 w1 = *(const float4*)&W3s[(k + kk) * 128 + c0 + 4];
                accA[0] += av[kk] * w0.x; accA[1] += av[kk] * w0.y;
                accA[2] += av[kk] * w0.z; accA[3] += av[kk] * w0.w;
                accA[4] += av[kk] * w1.x; accA[5] += av[kk] * w1.y;
                accA[6] += av[kk] * w1.z; accA[7] += av[kk] * w1.w;
                accB[0] += bv[kk] * w0.x; accB[1] += bv[kk] * w0.y;
                accB[2] += bv[kk] * w0.z; accB[3] += bv[kk] * w0.w;
                accB[4] += bv[kk] * w1.x; accB[5] += bv[kk] * w1.y;
                accB[6] += bv[kk] * w1.z; accB[7] += bv[kk] * w1.w;
            }
        }

        if (vA) {
            *(float4*)&g_Y[(size_t)edA.x * 256 + half * 128 + c0] =
                make_float4(accA[0], accA[1], accA[2], accA[3]);
            *(float4*)&g_Y[(size_t)edA.x * 256 + half * 128 + c0 + 4] =
                make_float4(accA[4], accA[5], accA[6], accA[7]);
#pragma unroll
            for (int q = 0; q < 8; q++) { rs[q] += accA[q]; rq[q] += accA[q] * accA[q]; }
        }
        if (vB) {
            *(float4*)&g_Y[(size_t)edB.x * 256 + half * 128 + c0] =
                make_float4(accB[0], accB[1], accB[2], accB[3]);
            *(float4*)&g_Y[(size_t)edB.x * 256 + half * 128 + c0 + 4] =
                make_float4(accB[4], accB[5], accB[6], accB[7]);
#pragma unroll
            for (int q = 0; q < 8; q++) { rs[q] += accB[q]; rq[q] += accB[q] * accB[q]; }
        }
    }

    __syncthreads();
#pragma unroll
    for (int q = 0; q < 8; q++) {
        atomicAdd(&ssum[c0 + q], rs[q]);
        atomicAdd(&ssq[c0 + q],  rq[q]);
    }
    __syncthreads();
    atomicAdd(&g_sum1[half * 128 + t], (double)ssum[t]);
    atomicAdd(&g_sq1 [half * 128 + t], (double)ssq[t]);
}

// ---------------- kernel 4: finalize BN1 ----------------
__global__ void k_fin1(const float* __restrict__ gamma1, const float* __restrict__ beta1) {
    int c = threadIdx.x;  // 256
    double cnt = (double)g_nedges;
    double m = g_sum1[c] / cnt;
    double v = g_sq1[c] / cnt - m * m;
    float sc = gamma1[c] * rsqrtf(fmaxf((float)v, 0.f) + EPS_F);
    g_sc1[c] = sc;
    g_sh1[c] = beta1[c] - (float)m * sc;
}

// ---------------- kernel 5: BN1 affine + sigmoid*softplus + neighbor sum + BN2 stats ----------------
__global__ void k_act(const float* __restrict__ mask) {
    int c = threadIdx.x;  // 128
    float scf = g_sc1[c],       shf = g_sh1[c];
    float scc = g_sc1[128 + c], shc = g_sh1[128 + c];
    float s2 = 0.f, q2 = 0.f;
    for (int i = blockIdx.x; i < N_ATOMS; i += gridDim.x) {
        float s = 0.f;
#pragma unroll 1
        for (int j = 0; j < 12; j++) {
            float mk = mask[i * 12 + j];
            if (mk > 0.5f) {
                size_t row = (size_t)i * 12 + j;
                float yf = g_Y[row * 256 + c]       * scf + shf;
                float yc = g_Y[row * 256 + 128 + c] * scc + shc;
                s += sigmoid_f(yf) * softplus_f(yc);
            }
        }
        g_NS[(size_t)i * 128 + c] = s;
        s2 += s; q2 += s * s;
    }
    atomicAdd(&g_sum2[c], (double)s2);
    atomicAdd(&g_sq2[c],  (double)q2);
}

// ---------------- kernel 6: finalize BN2 ----------------
__global__ void k_fin2(const float* __restrict__ gamma2, const float* __restrict__ beta2) {
    int c = threadIdx.x;  // 128
    double m = g_sum2[c] / (double)N_ATOMS;
    double v = g_sq2[c] / (double)N_ATOMS - m * m;
    float sc = gamma2[c] * rsqrtf(fmaxf((float)v, 0.f) + EPS_F);
    g_sc2[c] = sc;
    g_sh2[c] = beta2[c] - (float)m * sc;
}

// ---------------- kernel 7: output = softplus(atom + BN2(nbr_sumed)) ----------------
__global__ void k_out(const float* __restrict__ atom, float* __restrict__ out) {
    int idx = blockIdx.x * blockDim.x + threadIdx.x;
    if (idx < N_ATOMS * 128) {
        int c = idx & 127;
        float v = g_NS[idx] * g_sc2[c] + g_sh2[c] + atom[idx];
        out[idx] = softplus_f(v);
    }
}

// ---------------- launcher ----------------
extern "C" void kernel_launch(void* const* d_in, const int* in_sizes, int n_in,
                              void* d_out, int out_size) {
    const float* atom    = (const float*)d_in[0];
    const float* nbr_fea = (const float*)d_in[1];
    const int*   nbr_idx = (const int*)  d_in[2];
    const float* mask    = (const float*)d_in[3];
    const float* W       = (const float*)d_in[4];
    const float* b       = (const float*)d_in[5];
    const float* gamma1  = (const float*)d_in[6];
    const float* beta1   = (const float*)d_in[7];
    const float* gamma2  = (const float*)d_in[8];
    const float* beta2   = (const float*)d_in[9];
    float* out = (float*)d_out;

    k_zero   <<<1, 256>>>();
    k_compact<<<(NM_ROWS + 255) / 256, 256>>>(mask, nbr_idx);
    k_gemmP  <<<dim3(391, 4), 256>>>(atom, W);
    k_edge   <<<dim3(888, 2), 128>>>(nbr_fea, W, b);
    k_fin1   <<<1, 256>>>(gamma1, beta1);
    k_act    <<<1480, 128>>>(mask);
    k_fin2   <<<1, 128>>>(gamma2, beta2);
    k_out    <<<(N_ATOMS * 128 + 255) / 256, 256>>>(atom, out);
}